// round 3
// baseline (speedup 1.0000x reference)
#include <cuda_runtime.h>
#include <math.h>

// ---------------- constants ----------------
#define EPSF 1e-8f
#define BC   32
#define HW   262144   // 512*512

// reversed db4 decomposition filters:
// RL[k] = DEC_LO[7-k],  RH[k] = DEC_HI[7-k] = DEC_LO[k] * (k odd ? -1 : +1)
__constant__ float c_RL[8] = {
     0.23037781330885523f,  0.7148465705525415f,   0.6308807679295904f,
    -0.02798376941698385f, -0.18703481171888114f,  0.030841381835986965f,
     0.032883011666982945f, -0.010597401784997278f };
__constant__ float c_RH[8] = {
    -0.010597401784997278f, -0.032883011666982945f, 0.030841381835986965f,
     0.18703481171888114f,  -0.02798376941698385f,  -0.6308807679295904f,
     0.7148465705525415f,   -0.23037781330885523f };

// level sizes: 512 -> 259 -> 133 -> 70 -> 38, padded strides for 8B alignment
#define M1 259
#define M2 133
#define M3 70
#define M4 38
#define S1 260
#define S2 134
#define S3 70
#define S4 38

__device__ __align__(16) float g_cA1[BC * M1 * S1];
__device__ __align__(16) float g_m1 [BC * M1 * S1];
__device__ __align__(16) float g_cA2[BC * M2 * S2];
__device__ __align__(16) float g_m2 [BC * M2 * S2];
__device__ __align__(16) float g_cA3[BC * M3 * S3];
__device__ __align__(16) float g_m3 [BC * M3 * S3];
__device__ __align__(16) float g_cA4[BC * M4 * S4];
__device__ __align__(16) float g_m4 [BC * M4 * S4];
__device__ __align__(16) float g_sw [64];           // sigmoid(t_emb @ gate_w), [16,4]

// ---------------- gate: sigmoid(t_emb @ gate_w) ----------------
__global__ void gate_kernel(const float* __restrict__ t_emb,
                            const float* __restrict__ gate_w)
{
    int i = threadIdx.x;          // 0..63
    int b = i >> 2, s = i & 3;
    float acc = 0.f;
    #pragma unroll 8
    for (int k = 0; k < 64; k++)
        acc = fmaf(__ldg(t_emb + b * 64 + k), __ldg(gate_w + k * 4 + s), acc);
    g_sw[i] = 1.f / (1.f + expf(-acc));
}

// symmetric-extension index (pad(7,7,'symmetric')[...,1:]):  t = 2*out - 6 + k
__device__ __forceinline__ int eidx(int t, int N)
{
    if (t < 0)  return -1 - t;
    if (t >= N) return 2 * N - 1 - t;
    return t;
}

// ---------------- one DWT level: in [BC,N,INS] -> cA,mag [BC,M,OUTS] ----------------
template<int N, int INS, int M, int OUTS>
__global__ void __launch_bounds__(256)
dwt_kernel(const float* __restrict__ in,
           float* __restrict__ outA, float* __restrict__ outM)
{
    int jo = blockIdx.x * 32 + threadIdx.x;
    int io = blockIdx.y * 8  + threadIdx.y;
    int bc = blockIdx.z;
    if (jo >= M || io >= M) return;

    const float* img = in + (size_t)bc * N * INS;
    int cbase = 2 * jo - 6;
    int rbase = 2 * io - 6;

    float rowlo[8], rowhi[8];

    if (cbase >= 0 && cbase + 7 < N && rbase >= 0 && rbase + 7 < N) {
        // interior fast path: contiguous, 8B-aligned (cbase even, INS even or row offset even)
        const float* p = img + (size_t)rbase * INS + cbase;
        #pragma unroll
        for (int r = 0; r < 8; r++) {
            const float2* q = reinterpret_cast<const float2*>(p + (size_t)r * INS);
            float lo = 0.f, hi = 0.f;
            #pragma unroll
            for (int h = 0; h < 4; h++) {
                float2 v = __ldg(q + h);
                lo = fmaf(v.x, c_RL[2 * h], lo); lo = fmaf(v.y, c_RL[2 * h + 1], lo);
                hi = fmaf(v.x, c_RH[2 * h], hi); hi = fmaf(v.y, c_RH[2 * h + 1], hi);
            }
            rowlo[r] = lo; rowhi[r] = hi;
        }
    } else {
        int ci[8], ri[8];
        #pragma unroll
        for (int k = 0; k < 8; k++) {
            ci[k] = eidx(cbase + k, N);
            ri[k] = eidx(rbase + k, N);
        }
        #pragma unroll
        for (int r = 0; r < 8; r++) {
            const float* row = img + (size_t)ri[r] * INS;
            float lo = 0.f, hi = 0.f;
            #pragma unroll
            for (int k = 0; k < 8; k++) {
                float v = __ldg(row + ci[k]);
                lo = fmaf(v, c_RL[k], lo);
                hi = fmaf(v, c_RH[k], hi);
            }
            rowlo[r] = lo; rowhi[r] = hi;
        }
    }

    float ll = 0.f, lh = 0.f, hl = 0.f, hh = 0.f;
    #pragma unroll
    for (int r = 0; r < 8; r++) {
        ll = fmaf(rowlo[r], c_RL[r], ll);
        lh = fmaf(rowlo[r], c_RH[r], lh);
        hl = fmaf(rowhi[r], c_RL[r], hl);
        hh = fmaf(rowhi[r], c_RH[r], hh);
    }

    size_t o = (size_t)bc * M * OUTS + (size_t)io * OUTS + jo;
    outA[o] = ll;
    outM[o] = sqrtf(fmaf(lh, lh, fmaf(hl, hl, fmaf(hh, hh, EPSF))));
}

// ---------------- fused upsample + merge + gate ----------------
__device__ __forceinline__ void coord(int o, int n, int& i0, int& i1, float& f)
{
    // jax.image.resize 'linear' upsampling == half-pixel bilinear, clamp-to-edge
    float s  = (o + 0.5f) * (n * (1.0f / 512.0f)) - 0.5f;
    float fl = floorf(s);
    f = s - fl;
    int i = (int)fl;
    i0 = i < 0 ? 0 : i;
    int j = i + 1;
    i1 = j > n - 1 ? n - 1 : j;
}

__device__ __forceinline__ float bil(const float* __restrict__ p, int stride,
                                     int y0, int y1, float fy,
                                     int x0, int x1, float fx)
{
    const float* r0 = p + (size_t)y0 * stride;
    const float* r1 = p + (size_t)y1 * stride;
    float v00 = __ldg(r0 + x0), v01 = __ldg(r0 + x1);
    float v10 = __ldg(r1 + x0), v11 = __ldg(r1 + x1);
    float a = v00 + (v01 - v00) * fx;
    float b = v10 + (v11 - v10) * fx;
    return a + (b - a) * fy;
}

__global__ void __launch_bounds__(256)
fuse_kernel(float* __restrict__ out)
{
    int x  = blockIdx.x * 256 + threadIdx.x;   // 0..511
    int y  = blockIdx.y;                       // 0..511
    int bc = blockIdx.z;                       // 0..31
    int b = bc >> 1, c = bc & 1;

    int y0, y1, x0, x1; float fy, fx;

    // n = 38 : cA and mag4 share coordinates
    coord(y, M4, y0, y1, fy); coord(x, M4, x0, x1, fx);
    const float* pA = g_cA4 + (size_t)bc * M4 * S4;
    const float* p4 = g_m4  + (size_t)bc * M4 * S4;
    float f0 = 0.5f * (bil(pA, S4, y0, y1, fy, x0, x1, fx) +
                       bil(p4, S4, y0, y1, fy, x0, x1, fx));

    coord(y, M3, y0, y1, fy); coord(x, M3, x0, x1, fx);
    float f1 = bil(g_m3 + (size_t)bc * M3 * S3, S3, y0, y1, fy, x0, x1, fx);

    coord(y, M2, y0, y1, fy); coord(x, M2, x0, x1, fx);
    float f2 = bil(g_m2 + (size_t)bc * M2 * S2, S2, y0, y1, fy, x0, x1, fx);

    coord(y, M1, y0, y1, fy); coord(x, M1, x0, x1, fx);
    float f3 = bil(g_m1 + (size_t)bc * M1 * S1, S1, y0, y1, fy, x0, x1, fx);

    const float* sw = g_sw + b * 4;
    size_t base = (((size_t)(b * 8 + c * 4)) * 512 + y) * 512 + x;
    out[base           ] = f0 * sw[0];
    out[base +     HW  ] = f1 * sw[1];
    out[base + 2 * HW  ] = f2 * sw[2];
    out[base + 3 * HW  ] = f3 * sw[3];
}

// ---------------- launch ----------------
extern "C" void kernel_launch(void* const* d_in, const int* in_sizes, int n_in,
                              void* d_out, int out_size)
{
    const float* image  = (const float*)d_in[0];
    const float* t_emb  = (const float*)d_in[1];
    const float* gate_w = (const float*)d_in[2];
    float* out = (float*)d_out;

    float *cA1, *m1, *cA2, *m2, *cA3, *m3, *cA4, *m4;
    cudaGetSymbolAddress((void**)&cA1, g_cA1);
    cudaGetSymbolAddress((void**)&m1,  g_m1);
    cudaGetSymbolAddress((void**)&cA2, g_cA2);
    cudaGetSymbolAddress((void**)&m2,  g_m2);
    cudaGetSymbolAddress((void**)&cA3, g_cA3);
    cudaGetSymbolAddress((void**)&m3,  g_m3);
    cudaGetSymbolAddress((void**)&cA4, g_cA4);
    cudaGetSymbolAddress((void**)&m4,  g_m4);

    gate_kernel<<<1, 64>>>(t_emb, gate_w);

    dim3 blk(32, 8);
    {   dim3 g((M1 + 31) / 32, (M1 + 7) / 8, BC);
        dwt_kernel<512, 512, M1, S1><<<g, blk>>>(image, cA1, m1); }
    {   dim3 g((M2 + 31) / 32, (M2 + 7) / 8, BC);
        dwt_kernel<M1, S1, M2, S2><<<g, blk>>>(cA1, cA2, m2); }
    {   dim3 g((M3 + 31) / 32, (M3 + 7) / 8, BC);
        dwt_kernel<M2, S2, M3, S3><<<g, blk>>>(cA2, cA3, m3); }
    {   dim3 g((M4 + 31) / 32, (M4 + 7) / 8, BC);
        dwt_kernel<M3, S3, M4, S4><<<g, blk>>>(cA3, cA4, m4); }

    fuse_kernel<<<dim3(2, 512, BC), 256>>>(out);
}

// round 6
// speedup vs baseline: 1.0995x; 1.0995x over previous
#include <cuda_runtime.h>
#include <math.h>

// ---------------- constants ----------------
#define EPSF 1e-8f
#define BC   32
#define HW   262144   // 512*512

// reversed db4 decomposition filters:
// RL[k] = DEC_LO[7-k],  RH[k] = DEC_HI[7-k] = DEC_LO[k] * (k odd ? -1 : +1)
__constant__ float c_RL[8] = {
     0.23037781330885523f,  0.7148465705525415f,   0.6308807679295904f,
    -0.02798376941698385f, -0.18703481171888114f,  0.030841381835986965f,
     0.032883011666982945f, -0.010597401784997278f };
__constant__ float c_RH[8] = {
    -0.010597401784997278f, -0.032883011666982945f, 0.030841381835986965f,
     0.18703481171888114f,  -0.02798376941698385f,  -0.6308807679295904f,
     0.7148465705525415f,   -0.23037781330885523f };

// level sizes: 512 -> 259 -> 133 -> 70 -> 38, padded (even) strides
#define M1 259
#define M2 133
#define M3 70
#define M4 38
#define S1 260
#define S2 134
#define S3 70
#define S4 38

__device__ __align__(16) float g_cA1[BC * M1 * S1];
__device__ __align__(16) float g_m1 [BC * M1 * S1];
__device__ __align__(16) float g_cA2[BC * M2 * S2];
__device__ __align__(16) float g_m2 [BC * M2 * S2];
__device__ __align__(16) float g_m3 [BC * M3 * S3];
__device__ __align__(16) float g_cA4[BC * M4 * S4];
__device__ __align__(16) float g_m4 [BC * M4 * S4];
__device__ __align__(16) float g_sw [64];                 // sigmoid(t_emb @ gate_w)
// x-upsampled (and gated) rows: per bc, 500 rows (38+70+133+259) x 512
__device__ __align__(16) float g_up [BC * 500 * 512];

// ---------------- gate: sigmoid(t_emb @ gate_w) ----------------
__global__ void gate_kernel(const float* __restrict__ t_emb,
                            const float* __restrict__ gate_w)
{
    int i = threadIdx.x;          // 0..63
    int b = i >> 2, s = i & 3;
    float acc = 0.f;
    #pragma unroll 8
    for (int k = 0; k < 64; k++)
        acc = fmaf(__ldg(t_emb + b * 64 + k), __ldg(gate_w + k * 4 + s), acc);
    g_sw[i] = 1.f / (1.f + expf(-acc));
}

// symmetric-extension index (pad(7,7,'symmetric')[...,1:]):  t = 2*out - 6 + k
__device__ __forceinline__ int eidx(int t, int N)
{
    if (t < 0)  return -1 - t;
    if (t >= N) return 2 * N - 1 - t;
    return t;
}

// ---------------- 4-row group DWT: computes outputs (io0..io0+3, jo) ----------------
// src: [N rows, stride INS].  Produces ll[4] (approx) and mg[4] (detail magnitude).
// INS must be even for the interior float2 fast path.
__device__ __forceinline__ void dwt_group4(const float* __restrict__ src,
                                           int N, int INS, int jo, int io0,
                                           float ll[4], float mg[4])
{
    float lh[4], hl[4], hh[4];
    #pragma unroll
    for (int o = 0; o < 4; o++) { ll[o] = 0.f; lh[o] = 0.f; hl[o] = 0.f; hh[o] = 0.f; }

    int cb = 2 * jo - 6;
    int rb = 2 * io0 - 6;
    bool cint = (cb >= 0) && (cb + 7 < N);

    int ci[8];
    if (!cint) {
        #pragma unroll
        for (int k = 0; k < 8; k++) ci[k] = eidx(cb + k, N);
    }

    #pragma unroll
    for (int r = 0; r < 14; r++) {
        int ri = eidx(rb + r, N);
        const float* row = src + (size_t)ri * INS;
        float lo = 0.f, hi = 0.f;
        if (cint) {
            const float2* q = reinterpret_cast<const float2*>(row + cb);
            #pragma unroll
            for (int h = 0; h < 4; h++) {
                float2 v = q[h];
                lo = fmaf(v.x, c_RL[2 * h], lo); lo = fmaf(v.y, c_RL[2 * h + 1], lo);
                hi = fmaf(v.x, c_RH[2 * h], hi); hi = fmaf(v.y, c_RH[2 * h + 1], hi);
            }
        } else {
            #pragma unroll
            for (int k = 0; k < 8; k++) {
                float v = row[ci[k]];
                lo = fmaf(v, c_RL[k], lo);
                hi = fmaf(v, c_RH[k], hi);
            }
        }
        #pragma unroll
        for (int o = 0; o < 4; o++) {
            int k = r - 2 * o;
            if (k >= 0 && k < 8) {
                ll[o] = fmaf(lo, c_RL[k], ll[o]);
                lh[o] = fmaf(lo, c_RH[k], lh[o]);
                hl[o] = fmaf(hi, c_RL[k], hl[o]);
                hh[o] = fmaf(hi, c_RH[k], hh[o]);
            }
        }
    }
    #pragma unroll
    for (int o = 0; o < 4; o++)
        mg[o] = sqrtf(fmaf(lh[o], lh[o], fmaf(hl[o], hl[o], fmaf(hh[o], hh[o], EPSF))));
}

// ---------------- one DWT level (used for levels 1 and 2) ----------------
template<int N, int INS, int M, int OUTS>
__global__ void __launch_bounds__(256)
dwt_kernel(const float* __restrict__ in,
           float* __restrict__ outA, float* __restrict__ outM)
{
    int jo  = blockIdx.x * 32 + threadIdx.x;
    int io0 = (blockIdx.y * 8 + threadIdx.y) * 4;
    int bc  = blockIdx.z;
    if (jo >= M || io0 >= M) return;

    float ll[4], mg[4];
    dwt_group4(in + (size_t)bc * N * INS, N, INS, jo, io0, ll, mg);

    #pragma unroll
    for (int o = 0; o < 4; o++) {
        int io = io0 + o;
        if (io < M) {
            size_t off = (size_t)bc * M * OUTS + (size_t)io * OUTS + jo;
            outA[off] = ll[o];
            outM[off] = mg[o];
        }
    }
}

// ---------------- merged levels 3+4: one block per bc, cA3 in smem ----------------
__global__ void __launch_bounds__(512)
tail_kernel(const float* __restrict__ cA2,
            float* __restrict__ m3, float* __restrict__ cA4, float* __restrict__ m4)
{
    __shared__ float sA3[M3 * 72];     // stride 72 (even)
    int bc = blockIdx.x;
    int t  = threadIdx.x;
    const float* src2 = cA2 + (size_t)bc * M2 * S2;

    // level 3: 70x70 outputs as 70 jo x 18 row-groups
    const int NG3 = 70 * 18;
    for (int g = t; g < NG3; g += 512) {
        int jo  = g % 70;
        int io0 = (g / 70) * 4;
        float ll[4], mg[4];
        dwt_group4(src2, M2, S2, jo, io0, ll, mg);
        #pragma unroll
        for (int o = 0; o < 4; o++) {
            int io = io0 + o;
            if (io < M3) {
                sA3[io * 72 + jo] = ll[o];
                m3[(size_t)bc * M3 * S3 + io * S3 + jo] = mg[o];
            }
        }
    }
    __syncthreads();

    // level 4: 38x38 outputs as 38 jo x 10 row-groups, input from smem
    const int NG4 = 38 * 10;
    for (int g = t; g < NG4; g += 512) {
        int jo  = g % 38;
        int io0 = (g / 38) * 4;
        float ll[4], mg[4];
        dwt_group4(sA3, M3, 72, jo, io0, ll, mg);
        #pragma unroll
        for (int o = 0; o < 4; o++) {
            int io = io0 + o;
            if (io < M4) {
                size_t off = (size_t)bc * M4 * S4 + io * S4 + jo;
                cA4[off] = ll[o];
                m4[off]  = mg[o];
            }
        }
    }
}

// ---------------- upsample coordinates (jax.image.resize 'linear') ----------------
__device__ __forceinline__ void coord(int o, int n, int& i0, int& i1, float& f)
{
    float s  = (o + 0.5f) * (n * (1.0f / 512.0f)) - 0.5f;
    float fl = floorf(s);
    f = s - fl;
    int i = (int)fl;
    i0 = i < 0 ? 0 : i;
    int j = i + 1;
    i1 = j > n - 1 ? n - 1 : j;
}

// ---------------- pass 1: x-upsample each source row to 512, gate folded in ----------
// g_up layout per bc: rows [0,38)=s0 (0.5*(cA4+m4)), [38,108)=s1(m3), [108,241)=s2(m2),
// [241,500)=s3(m1). grid (500, BC), block 128, 4 x per thread.
__global__ void __launch_bounds__(128)
upx_kernel()
{
    int rg = blockIdx.x;
    int bc = blockIdx.y;
    int b  = bc >> 1;

    int n, s;
    const float* srcA;
    const float* srcB = 0;
    if (rg < 38) {
        s = 0; n = M4; int row = rg;
        srcA = g_cA4 + (size_t)bc * M4 * S4 + row * S4;
        srcB = g_m4  + (size_t)bc * M4 * S4 + row * S4;
    } else if (rg < 108) {
        s = 1; n = M3; int row = rg - 38;
        srcA = g_m3 + (size_t)bc * M3 * S3 + row * S3;
    } else if (rg < 241) {
        s = 2; n = M2; int row = rg - 108;
        srcA = g_m2 + (size_t)bc * M2 * S2 + (size_t)row * S2;
    } else {
        s = 3; n = M1; int row = rg - 241;
        srcA = g_m1 + (size_t)bc * M1 * S1 + (size_t)row * S1;
    }
    float w = g_sw[b * 4 + s];
    if (s == 0) w *= 0.5f;

    int xb = threadIdx.x * 4;
    float res[4];
    #pragma unroll
    for (int i = 0; i < 4; i++) {
        int x = xb + i;
        int x0, x1; float fx;
        coord(x, n, x0, x1, fx);
        float a0 = srcA[x0];
        float v  = a0 + (srcA[x1] - a0) * fx;
        if (srcB) {
            float b0 = srcB[x0];
            v += b0 + (srcB[x1] - b0) * fx;
        }
        res[i] = v * w;
    }
    float4 o4 = make_float4(res[0], res[1], res[2], res[3]);
    reinterpret_cast<float4*>(g_up + ((size_t)bc * 500 + rg) * 512)[threadIdx.x] = o4;
}

// ---------------- pass 2: y-upsample, fully coalesced float4 streaming ----------------
__global__ void __launch_bounds__(128)
upy_kernel(float* __restrict__ out)
{
    int y  = blockIdx.x;
    int bc = blockIdx.y;
    int b  = bc >> 1, c = bc & 1;
    int tx = threadIdx.x;

    const int ns[4]   = {M4, M3, M2, M1};
    const int offr[4] = {0, 38, 108, 241};
    const float* upb = g_up + (size_t)bc * 500 * 512;

    #pragma unroll
    for (int s = 0; s < 4; s++) {
        int y0, y1; float fy;
        coord(y, ns[s], y0, y1, fy);
        const float4* r0 = reinterpret_cast<const float4*>(upb + (size_t)(offr[s] + y0) * 512);
        const float4* r1 = reinterpret_cast<const float4*>(upb + (size_t)(offr[s] + y1) * 512);
        float4 a = r0[tx], d = r1[tx];
        float4 v;
        v.x = a.x + (d.x - a.x) * fy;
        v.y = a.y + (d.y - a.y) * fy;
        v.z = a.z + (d.z - a.z) * fy;
        v.w = a.w + (d.w - a.w) * fy;
        size_t base = (((size_t)(b * 8 + c * 4 + s)) * 512 + y) * 512;
        reinterpret_cast<float4*>(out + base)[tx] = v;
    }
}

// ---------------- launch ----------------
extern "C" void kernel_launch(void* const* d_in, const int* in_sizes, int n_in,
                              void* d_out, int out_size)
{
    const float* image  = (const float*)d_in[0];
    const float* t_emb  = (const float*)d_in[1];
    const float* gate_w = (const float*)d_in[2];
    float* out = (float*)d_out;

    float *cA1, *m1, *cA2, *m2, *m3, *cA4, *m4;
    cudaGetSymbolAddress((void**)&cA1, g_cA1);
    cudaGetSymbolAddress((void**)&m1,  g_m1);
    cudaGetSymbolAddress((void**)&cA2, g_cA2);
    cudaGetSymbolAddress((void**)&m2,  g_m2);
    cudaGetSymbolAddress((void**)&m3,  g_m3);
    cudaGetSymbolAddress((void**)&cA4, g_cA4);
    cudaGetSymbolAddress((void**)&m4,  g_m4);

    gate_kernel<<<1, 64>>>(t_emb, gate_w);

    dim3 blk(32, 8);
    {   dim3 g((M1 + 31) / 32, (M1 + 31) / 32, BC);
        dwt_kernel<512, 512, M1, S1><<<g, blk>>>(image, cA1, m1); }
    {   dim3 g((M2 + 31) / 32, (M2 + 31) / 32, BC);
        dwt_kernel<M1, S1, M2, S2><<<g, blk>>>(cA1, cA2, m2); }

    tail_kernel<<<BC, 512>>>(cA2, m3, cA4, m4);

    upx_kernel<<<dim3(500, BC), 128>>>();
    upy_kernel<<<dim3(512, BC), 128>>>(out);
}

// round 7
// speedup vs baseline: 1.1808x; 1.0739x over previous
#include <cuda_runtime.h>
#include <math.h>

// ---------------- constants ----------------
#define EPSF 1e-8f
#define BC   32
#define HW   262144   // 512*512

// reversed db4 decomposition filters:
// RL[k] = DEC_LO[7-k],  RH[k] = DEC_HI[7-k] = DEC_LO[k] * (k odd ? -1 : +1)
__constant__ float c_RL[8] = {
     0.23037781330885523f,  0.7148465705525415f,   0.6308807679295904f,
    -0.02798376941698385f, -0.18703481171888114f,  0.030841381835986965f,
     0.032883011666982945f, -0.010597401784997278f };
__constant__ float c_RH[8] = {
    -0.010597401784997278f, -0.032883011666982945f, 0.030841381835986965f,
     0.18703481171888114f,  -0.02798376941698385f,  -0.6308807679295904f,
     0.7148465705525415f,   -0.23037781330885523f };

// level sizes: 512 -> 259 -> 133 -> 70 -> 38, padded (even) strides
#define M1 259
#define M2 133
#define M3 70
#define M4 38
#define S1 260
#define S2 134
#define S3 70
#define S4 38

__device__ __align__(16) float g_cA1[BC * M1 * S1];
__device__ __align__(16) float g_m1 [BC * M1 * S1];
__device__ __align__(16) float g_cA2[BC * M2 * S2];
__device__ __align__(16) float g_m2 [BC * M2 * S2];
__device__ __align__(16) float g_m3 [BC * M3 * S3];
__device__ __align__(16) float g_cA4[BC * M4 * S4];
__device__ __align__(16) float g_m4 [BC * M4 * S4];
__device__ __align__(16) float g_sw [64];                 // sigmoid(t_emb @ gate_w)

// ---------------- gate: sigmoid(t_emb @ gate_w) ----------------
__global__ void gate_kernel(const float* __restrict__ t_emb,
                            const float* __restrict__ gate_w)
{
    int i = threadIdx.x;          // 0..63
    int b = i >> 2, s = i & 3;
    float acc = 0.f;
    #pragma unroll 8
    for (int k = 0; k < 64; k++)
        acc = fmaf(__ldg(t_emb + b * 64 + k), __ldg(gate_w + k * 4 + s), acc);
    g_sw[i] = 1.f / (1.f + expf(-acc));
}

// symmetric-extension index (pad(7,7,'symmetric')[...,1:]):  t = 2*out - 6 + k
__device__ __forceinline__ int eidx(int t, int N)
{
    if (t < 0)  return -1 - t;
    if (t >= N) return 2 * N - 1 - t;
    return t;
}

// ---------------- 4-row group DWT (levels 1 & 2, FMA-bound) ----------------
__device__ __forceinline__ void dwt_group4(const float* __restrict__ src,
                                           int N, int INS, int jo, int io0,
                                           float ll[4], float mg[4])
{
    float lh[4], hl[4], hh[4];
    #pragma unroll
    for (int o = 0; o < 4; o++) { ll[o] = 0.f; lh[o] = 0.f; hl[o] = 0.f; hh[o] = 0.f; }

    int cb = 2 * jo - 6;
    int rb = 2 * io0 - 6;
    bool cint = (cb >= 0) && (cb + 7 < N);

    int ci[8];
    if (!cint) {
        #pragma unroll
        for (int k = 0; k < 8; k++) ci[k] = eidx(cb + k, N);
    }

    #pragma unroll
    for (int r = 0; r < 14; r++) {
        int ri = eidx(rb + r, N);
        const float* row = src + (size_t)ri * INS;
        float lo = 0.f, hi = 0.f;
        if (cint) {
            const float2* q = reinterpret_cast<const float2*>(row + cb);
            #pragma unroll
            for (int h = 0; h < 4; h++) {
                float2 v = q[h];
                lo = fmaf(v.x, c_RL[2 * h], lo); lo = fmaf(v.y, c_RL[2 * h + 1], lo);
                hi = fmaf(v.x, c_RH[2 * h], hi); hi = fmaf(v.y, c_RH[2 * h + 1], hi);
            }
        } else {
            #pragma unroll
            for (int k = 0; k < 8; k++) {
                float v = row[ci[k]];
                lo = fmaf(v, c_RL[k], lo);
                hi = fmaf(v, c_RH[k], hi);
            }
        }
        #pragma unroll
        for (int o = 0; o < 4; o++) {
            int k = r - 2 * o;
            if (k >= 0 && k < 8) {
                ll[o] = fmaf(lo, c_RL[k], ll[o]);
                lh[o] = fmaf(lo, c_RH[k], lh[o]);
                hl[o] = fmaf(hi, c_RL[k], hl[o]);
                hh[o] = fmaf(hi, c_RH[k], hh[o]);
            }
        }
    }
    #pragma unroll
    for (int o = 0; o < 4; o++)
        mg[o] = sqrtf(fmaf(lh[o], lh[o], fmaf(hl[o], hl[o], fmaf(hh[o], hh[o], EPSF))));
}

template<int N, int INS, int M, int OUTS>
__global__ void __launch_bounds__(256)
dwt_kernel(const float* __restrict__ in,
           float* __restrict__ outA, float* __restrict__ outM)
{
    int jo  = blockIdx.x * 32 + threadIdx.x;
    int io0 = (blockIdx.y * 8 + threadIdx.y) * 4;
    int bc  = blockIdx.z;
    if (jo >= M || io0 >= M) return;

    float ll[4], mg[4];
    dwt_group4(in + (size_t)bc * N * INS, N, INS, jo, io0, ll, mg);

    #pragma unroll
    for (int o = 0; o < 4; o++) {
        int io = io0 + o;
        if (io < M) {
            size_t off = (size_t)bc * M * OUTS + (size_t)io * OUTS + jo;
            outA[off] = ll[o];
            outM[off] = mg[o];
        }
    }
}

// ---------------- 1-row DWT (latency-bound tiny levels) ----------------
// src row r of the logical N x N input is at src + (eidx(rb+r,N) - roff) * rstride.
__device__ __forceinline__ void dwt_one(const float* __restrict__ src,
                                        int N, int rstride, int roff,
                                        int jo, int io, float& outA, float& outM)
{
    int cb = 2 * jo - 6;
    int rb = 2 * io - 6;
    bool cint = (cb >= 0) && (cb + 7 < N);
    int ci[8];
    if (!cint) {
        #pragma unroll
        for (int k = 0; k < 8; k++) ci[k] = eidx(cb + k, N);
    }
    float ll = 0.f, lh = 0.f, hl = 0.f, hh = 0.f;
    #pragma unroll
    for (int r = 0; r < 8; r++) {
        int ri = eidx(rb + r, N) - roff;
        const float* row = src + (size_t)ri * rstride;
        float lo = 0.f, hi = 0.f;
        if (cint) {
            const float2* q = reinterpret_cast<const float2*>(row + cb);
            #pragma unroll
            for (int h = 0; h < 4; h++) {
                float2 v = q[h];
                lo = fmaf(v.x, c_RL[2 * h], lo); lo = fmaf(v.y, c_RL[2 * h + 1], lo);
                hi = fmaf(v.x, c_RH[2 * h], hi); hi = fmaf(v.y, c_RH[2 * h + 1], hi);
            }
        } else {
            #pragma unroll
            for (int k = 0; k < 8; k++) {
                float v = row[ci[k]];
                lo = fmaf(v, c_RL[k], lo);
                hi = fmaf(v, c_RH[k], hi);
            }
        }
        ll = fmaf(lo, c_RL[r], ll);
        lh = fmaf(lo, c_RH[r], lh);
        hl = fmaf(hi, c_RL[r], hl);
        hh = fmaf(hi, c_RH[r], hh);
    }
    outA = ll;
    outM = sqrtf(fmaf(lh, lh, fmaf(hl, hl, fmaf(hh, hh, EPSF))));
}

// ---------------- merged levels 3+4, 8 partitions per bc (256 CTAs) ----------------
__global__ void __launch_bounds__(256)
tail_kernel(const float* __restrict__ cA2,
            float* __restrict__ m3, float* __restrict__ cA4, float* __restrict__ m4)
{
    __shared__ __align__(16) float sA3[16 * 72];   // window of cA3, stride 72
    int blk = blockIdx.x;          // 0..255
    int bc  = blk >> 3;
    int p   = blk & 7;
    int t   = threadIdx.x;
    const float* src2 = cA2 + (size_t)bc * M2 * S2;

    // owned level-4 rows: [5p, min(5p+5, 38))
    int l4lo = 5 * p;
    int l4hi = min(5 * p + 5, M4);
    // cA3 rows needed by those level-4 rows: e(t) for t in [2*l4lo-6, 2*(l4hi-1)+1]
    int tmin = 2 * l4lo - 6;
    int tmax = 2 * (l4hi - 1) + 1;
    int rlo = max(0, tmin);
    int rhi = min(M3 - 1, tmax);
    if (tmin < 0)        rhi = max(rhi, -1 - tmin);
    if (tmax > M3 - 1)   rlo = min(rlo, 2 * M3 - 1 - tmax);
    // owned m3 rows: [9p, min(9p+9, 70))
    int olo = 9 * p;
    int ohi = min(9 * p + 9, M3);
    rlo = min(rlo, olo);
    rhi = max(rhi, ohi - 1);
    int nr = rhi - rlo + 1;        // <= 16 by construction

    // Phase A: compute cA3 rows [rlo, rhi], write owned m3 rows
    for (int g = t; g < nr * 70; g += 256) {
        int jo = g % 70;
        int io = rlo + g / 70;
        float ll, mg;
        dwt_one(src2, M2, S2, 0, jo, io, ll, mg);
        sA3[(io - rlo) * 72 + jo] = ll;
        if (io >= olo && io < ohi)
            m3[(size_t)bc * M3 * S3 + io * S3 + jo] = mg;
    }
    __syncthreads();

    // Phase B: level 4 on smem window
    int nout = (l4hi - l4lo) * 38;     // <= 190, single pass
    if (t < nout) {
        int jo = t % 38;
        int io = l4lo + t / 38;
        float ll, mg;
        dwt_one(sA3, M3, 72, rlo, jo, io, ll, mg);
        size_t off = (size_t)bc * M4 * S4 + io * S4 + jo;
        cA4[off] = ll;
        m4[off]  = mg;
    }
}

// ---------------- upsample coordinates (jax.image.resize 'linear') ----------------
__device__ __forceinline__ void coord(int o, int n, int& i0, int& i1, float& f)
{
    float s  = (o + 0.5f) * (n * (1.0f / 512.0f)) - 0.5f;
    float fl = floorf(s);
    f = s - fl;
    int i = (int)fl;
    i0 = i < 0 ? 0 : i;
    int j = i + 1;
    i1 = j > n - 1 ? n - 1 : j;
}

// ---------------- fused separable upsample + merge + gate ----------------
// grid (16 y-blocks, 32 bc), block 256. Per scale: stage <=18 x-upsampled
// (and gated) source rows in smem, then y-interp 32x512 outputs as float4.
__global__ void __launch_bounds__(256)
up_kernel(float* __restrict__ out)
{
    __shared__ __align__(16) float srow[18 * 512];   // 36 KB
    int ya  = blockIdx.x * 32;
    int bc  = blockIdx.y;
    int b   = bc >> 1, c = bc & 1;
    int tid = threadIdx.x;

    #pragma unroll
    for (int s = 0; s < 4; s++) {
        int n, stride;
        const float* srcA;
        const float* srcB = 0;
        if      (s == 0) { n = M4; stride = S4; srcA = g_cA4 + (size_t)bc * M4 * S4;
                                                srcB = g_m4  + (size_t)bc * M4 * S4; }
        else if (s == 1) { n = M3; stride = S3; srcA = g_m3 + (size_t)bc * M3 * S3; }
        else if (s == 2) { n = M2; stride = S2; srcA = g_m2 + (size_t)bc * M2 * S2; }
        else             { n = M1; stride = S1; srcA = g_m1 + (size_t)bc * M1 * S1; }

        float w = g_sw[b * 4 + s];
        if (s == 0) w *= 0.5f;

        float rr = n * (1.0f / 512.0f);
        int i0a  = (int)floorf((ya + 0.5f)  * rr - 0.5f);
        int i1b  = (int)floorf((ya + 31.5f) * rr - 0.5f) + 1;
        int rloC = max(i0a, 0);
        int rhiC = min(i1b, n - 1);
        int nst  = rhiC - rloC + 1;    // <= 18

        // x coords for the two column halves this thread owns
        int xA0, xA1, xB0, xB1; float fA, fB;
        coord(tid,       n, xA0, xA1, fA);
        coord(tid + 256, n, xB0, xB1, fB);

        for (int r = 0; r < nst; r++) {
            const float* rowA = srcA + (size_t)(rloC + r) * stride;
            float a0 = rowA[xA0];
            float vA = a0 + (rowA[xA1] - a0) * fA;
            float b0 = rowA[xB0];
            float vB = b0 + (rowA[xB1] - b0) * fB;
            if (srcB) {
                const float* rowB = srcB + (size_t)(rloC + r) * stride;
                float c0 = rowB[xA0];
                vA += c0 + (rowB[xA1] - c0) * fA;
                float c1 = rowB[xB0];
                vB += c1 + (rowB[xB1] - c1) * fB;
            }
            srow[r * 512 + tid]       = vA * w;
            srow[r * 512 + tid + 256] = vB * w;
        }
        __syncthreads();

        size_t obase = ((size_t)(b * 8 + c * 4 + s)) * HW;
        #pragma unroll 4
        for (int i = tid; i < 32 * 128; i += 256) {
            int ry = i >> 7, c4 = i & 127;
            int y = ya + ry;
            int y0, y1; float fy;
            coord(y, n, y0, y1, fy);
            const float4* r0 = reinterpret_cast<const float4*>(srow + (size_t)(y0 - rloC) * 512);
            const float4* r1 = reinterpret_cast<const float4*>(srow + (size_t)(y1 - rloC) * 512);
            float4 a = r0[c4], d = r1[c4], v;
            v.x = a.x + (d.x - a.x) * fy;
            v.y = a.y + (d.y - a.y) * fy;
            v.z = a.z + (d.z - a.z) * fy;
            v.w = a.w + (d.w - a.w) * fy;
            reinterpret_cast<float4*>(out + obase + (size_t)y * 512)[c4] = v;
        }
        __syncthreads();
    }
}

// ---------------- launch ----------------
extern "C" void kernel_launch(void* const* d_in, const int* in_sizes, int n_in,
                              void* d_out, int out_size)
{
    const float* image  = (const float*)d_in[0];
    const float* t_emb  = (const float*)d_in[1];
    const float* gate_w = (const float*)d_in[2];
    float* out = (float*)d_out;

    float *cA1, *m1, *cA2, *m2, *m3, *cA4, *m4;
    cudaGetSymbolAddress((void**)&cA1, g_cA1);
    cudaGetSymbolAddress((void**)&m1,  g_m1);
    cudaGetSymbolAddress((void**)&cA2, g_cA2);
    cudaGetSymbolAddress((void**)&m2,  g_m2);
    cudaGetSymbolAddress((void**)&m3,  g_m3);
    cudaGetSymbolAddress((void**)&cA4, g_cA4);
    cudaGetSymbolAddress((void**)&m4,  g_m4);

    gate_kernel<<<1, 64>>>(t_emb, gate_w);

    dim3 blk(32, 8);
    {   dim3 g((M1 + 31) / 32, (M1 + 31) / 32, BC);
        dwt_kernel<512, 512, M1, S1><<<g, blk>>>(image, cA1, m1); }
    {   dim3 g((M2 + 31) / 32, (M2 + 31) / 32, BC);
        dwt_kernel<M1, S1, M2, S2><<<g, blk>>>(cA1, cA2, m2); }

    tail_kernel<<<BC * 8, 256>>>(cA2, m3, cA4, m4);

    up_kernel<<<dim3(16, BC), 256>>>(out);
}

// round 9
// speedup vs baseline: 1.2505x; 1.0590x over previous
#include <cuda_runtime.h>
#include <math.h>

// ---------------- constants ----------------
#define EPSF 1e-8f
#define BC   32
#define HW   262144   // 512*512

// reversed db4 decomposition filters:
// RL[k] = DEC_LO[7-k],  RH[k] = DEC_HI[7-k] = DEC_LO[k] * (k odd ? -1 : +1)
__constant__ float c_RL[8] = {
     0.23037781330885523f,  0.7148465705525415f,   0.6308807679295904f,
    -0.02798376941698385f, -0.18703481171888114f,  0.030841381835986965f,
     0.032883011666982945f, -0.010597401784997278f };
__constant__ float c_RH[8] = {
    -0.010597401784997278f, -0.032883011666982945f, 0.030841381835986965f,
     0.18703481171888114f,  -0.02798376941698385f,  -0.6308807679295904f,
     0.7148465705525415f,   -0.23037781330885523f };
// interleaved (RL[k], RH[k]) pairs for f32x2 math, 8-byte aligned
__constant__ __align__(8) float c_Pf[16] = {
     0.23037781330885523f,  -0.010597401784997278f,
     0.7148465705525415f,   -0.032883011666982945f,
     0.6308807679295904f,    0.030841381835986965f,
    -0.02798376941698385f,   0.18703481171888114f,
    -0.18703481171888114f,  -0.02798376941698385f,
     0.030841381835986965f, -0.6308807679295904f,
     0.032883011666982945f,  0.7148465705525415f,
    -0.010597401784997278f, -0.23037781330885523f };

// level sizes: 512 -> 259 -> 133 -> 70 -> 38, padded (even) strides
#define M1 259
#define M2 133
#define M3 70
#define M4 38
#define S1 260
#define S2 134
#define S3 70
#define S4 38

__device__ __align__(16) float g_cA1[BC * M1 * S1];
__device__ __align__(16) float g_m1 [BC * M1 * S1];
__device__ __align__(16) float g_cA2[BC * M2 * S2];
__device__ __align__(16) float g_m2 [BC * M2 * S2];
__device__ __align__(16) float g_m3 [BC * M3 * S3];
__device__ __align__(16) float g_cA4[BC * M4 * S4];
__device__ __align__(16) float g_m4 [BC * M4 * S4];

// ---------------- f32x2 helpers ----------------
__device__ __forceinline__ unsigned long long bcast2(float a)
{
    unsigned long long r;
    asm("mov.b64 %0, {%1, %2};" : "=l"(r) : "f"(a), "f"(a));
    return r;
}
__device__ __forceinline__ unsigned long long fma2(unsigned long long a,
                                                   unsigned long long b,
                                                   unsigned long long c)
{
    unsigned long long d;
    asm("fma.rn.f32x2 %0, %1, %2, %3;" : "=l"(d) : "l"(a), "l"(b), "l"(c));
    return d;
}
__device__ __forceinline__ void unpk(unsigned long long v, float& a, float& b)
{
    asm("mov.b64 {%0, %1}, %2;" : "=f"(a), "=f"(b) : "l"(v));
}

// symmetric-extension index (pad(7,7,'symmetric')[...,1:]):  t = 2*out - 6 + k
__device__ __forceinline__ int eidx(int t, int N)
{
    if (t < 0)  return -1 - t;
    if (t >= N) return 2 * N - 1 - t;
    return t;
}

// ---------------- 4-row group DWT (levels 1 & 2), f32x2 packed ----------------
__device__ __forceinline__ void dwt_group4(const float* __restrict__ src,
                                           int N, int INS, int jo, int io0,
                                           float ll[4], float mg[4])
{
    const unsigned long long* cP =
        reinterpret_cast<const unsigned long long*>(c_Pf);
    unsigned long long A[4], B[4];   // A=(ll,lh)  B=(hl,hh)
    #pragma unroll
    for (int o = 0; o < 4; o++) { A[o] = 0ull; B[o] = 0ull; }

    int cb = 2 * jo - 6;
    int rb = 2 * io0 - 6;
    bool cint = (cb >= 0) && (cb + 7 < N);

    int ci[8];
    if (!cint) {
        #pragma unroll
        for (int k = 0; k < 8; k++) ci[k] = eidx(cb + k, N);
    }

    #pragma unroll
    for (int r = 0; r < 14; r++) {
        int ri = eidx(rb + r, N);
        const float* row = src + (size_t)ri * INS;
        float lo, hi;
        if (cint) {
            const float2* q = reinterpret_cast<const float2*>(row + cb);
            unsigned long long acc = 0ull;
            #pragma unroll
            for (int h = 0; h < 4; h++) {
                float2 v = q[h];
                acc = fma2(bcast2(v.x), cP[2 * h],     acc);
                acc = fma2(bcast2(v.y), cP[2 * h + 1], acc);
            }
            unpk(acc, lo, hi);
        } else {
            lo = 0.f; hi = 0.f;
            #pragma unroll
            for (int k = 0; k < 8; k++) {
                float v = row[ci[k]];
                lo = fmaf(v, c_RL[k], lo);
                hi = fmaf(v, c_RH[k], hi);
            }
        }
        unsigned long long lo2 = bcast2(lo), hi2 = bcast2(hi);
        #pragma unroll
        for (int o = 0; o < 4; o++) {
            int k = r - 2 * o;
            if (k >= 0 && k < 8) {
                A[o] = fma2(lo2, cP[k], A[o]);
                B[o] = fma2(hi2, cP[k], B[o]);
            }
        }
    }
    #pragma unroll
    for (int o = 0; o < 4; o++) {
        float l, lh, hl, hh;
        unpk(A[o], l, lh);
        unpk(B[o], hl, hh);
        ll[o] = l;
        mg[o] = sqrtf(fmaf(lh, lh, fmaf(hl, hl, fmaf(hh, hh, EPSF))));
    }
}

template<int N, int INS, int M, int OUTS>
__global__ void __launch_bounds__(256)
dwt_kernel(const float* __restrict__ in,
           float* __restrict__ outA, float* __restrict__ outM)
{
    int jo  = blockIdx.x * 32 + threadIdx.x;
    int io0 = (blockIdx.y * 8 + threadIdx.y) * 4;
    int bc  = blockIdx.z;
    if (jo >= M || io0 >= M) return;

    float ll[4], mg[4];
    dwt_group4(in + (size_t)bc * N * INS, N, INS, jo, io0, ll, mg);

    #pragma unroll
    for (int o = 0; o < 4; o++) {
        int io = io0 + o;
        if (io < M) {
            size_t off = (size_t)bc * M * OUTS + (size_t)io * OUTS + jo;
            outA[off] = ll[o];
            outM[off] = mg[o];
        }
    }
}

// ---------------- 1-row DWT (tiny levels), f32x2 packed ----------------
__device__ __forceinline__ void dwt_one(const float* __restrict__ src,
                                        int N, int rstride, int roff,
                                        int jo, int io, float& outA, float& outM)
{
    const unsigned long long* cP =
        reinterpret_cast<const unsigned long long*>(c_Pf);
    int cb = 2 * jo - 6;
    int rb = 2 * io - 6;
    bool cint = (cb >= 0) && (cb + 7 < N);
    int ci[8];
    if (!cint) {
        #pragma unroll
        for (int k = 0; k < 8; k++) ci[k] = eidx(cb + k, N);
    }
    unsigned long long A = 0ull, B = 0ull;
    #pragma unroll
    for (int r = 0; r < 8; r++) {
        int ri = eidx(rb + r, N) - roff;
        const float* row = src + (size_t)ri * rstride;
        float lo, hi;
        if (cint) {
            const float2* q = reinterpret_cast<const float2*>(row + cb);
            unsigned long long acc = 0ull;
            #pragma unroll
            for (int h = 0; h < 4; h++) {
                float2 v = q[h];
                acc = fma2(bcast2(v.x), cP[2 * h],     acc);
                acc = fma2(bcast2(v.y), cP[2 * h + 1], acc);
            }
            unpk(acc, lo, hi);
        } else {
            lo = 0.f; hi = 0.f;
            #pragma unroll
            for (int k = 0; k < 8; k++) {
                float v = row[ci[k]];
                lo = fmaf(v, c_RL[k], lo);
                hi = fmaf(v, c_RH[k], hi);
            }
        }
        A = fma2(bcast2(lo), cP[r], A);
        B = fma2(bcast2(hi), cP[r], B);
    }
    float ll, lh, hl, hh;
    unpk(A, ll, lh);
    unpk(B, hl, hh);
    outA = ll;
    outM = sqrtf(fmaf(lh, lh, fmaf(hl, hl, fmaf(hh, hh, EPSF))));
}

// ---------------- merged levels 3+4, 8 partitions per bc (256 CTAs) ----------------
__global__ void __launch_bounds__(256)
tail_kernel(const float* __restrict__ cA2,
            float* __restrict__ m3, float* __restrict__ cA4, float* __restrict__ m4)
{
    __shared__ __align__(16) float sA3[16 * 72];   // window of cA3, stride 72
    int blk = blockIdx.x;          // 0..255
    int bc  = blk >> 3;
    int p   = blk & 7;
    int t   = threadIdx.x;
    const float* src2 = cA2 + (size_t)bc * M2 * S2;

    // owned level-4 rows: [5p, min(5p+5, 38))
    int l4lo = 5 * p;
    int l4hi = min(5 * p + 5, M4);
    // cA3 rows needed: e(t) for t in [2*l4lo-6, 2*(l4hi-1)+1]
    int tmin = 2 * l4lo - 6;
    int tmax = 2 * (l4hi - 1) + 1;
    int rlo = max(0, tmin);
    int rhi = min(M3 - 1, tmax);
    if (tmin < 0)        rhi = max(rhi, -1 - tmin);
    if (tmax > M3 - 1)   rlo = min(rlo, 2 * M3 - 1 - tmax);
    // owned m3 rows: [9p, min(9p+9, 70))
    int olo = 9 * p;
    int ohi = min(9 * p + 9, M3);
    rlo = min(rlo, olo);
    rhi = max(rhi, ohi - 1);
    int nr = rhi - rlo + 1;        // <= 16 by construction

    // Phase A: compute cA3 rows [rlo, rhi], write owned m3 rows
    for (int g = t; g < nr * 70; g += 256) {
        int jo = g % 70;
        int io = rlo + g / 70;
        float ll, mg;
        dwt_one(src2, M2, S2, 0, jo, io, ll, mg);
        sA3[(io - rlo) * 72 + jo] = ll;
        if (io >= olo && io < ohi)
            m3[(size_t)bc * M3 * S3 + io * S3 + jo] = mg;
    }
    __syncthreads();

    // Phase B: level 4 on smem window
    int nout = (l4hi - l4lo) * 38;     // <= 190, single pass
    if (t < nout) {
        int jo = t % 38;
        int io = l4lo + t / 38;
        float ll, mg;
        dwt_one(sA3, M3, 72, rlo, jo, io, ll, mg);
        size_t off = (size_t)bc * M4 * S4 + io * S4 + jo;
        cA4[off] = ll;
        m4[off]  = mg;
    }
}

// ---------------- upsample coordinates (jax.image.resize 'linear') ----------------
__device__ __forceinline__ void coord(int o, int n, int& i0, int& i1, float& f)
{
    float s  = (o + 0.5f) * (n * (1.0f / 512.0f)) - 0.5f;
    float fl = floorf(s);
    f = s - fl;
    int i = (int)fl;
    i0 = i < 0 ? 0 : i;
    int j = i + 1;
    i1 = j > n - 1 ? n - 1 : j;
}

// ---------------- fused separable upsample + merge + gate ----------------
// grid (16 y-blocks, 32 bc, 4 scales), block 256.
// Stage <=18 x-upsampled source rows in smem, then y-interp 32x512 float4 stores.
// Gate (sigmoid(t_emb@gate_w)) computed in warp 0, applied at store stage.
__global__ void __launch_bounds__(256)
up_kernel(float* __restrict__ out,
          const float* __restrict__ t_emb, const float* __restrict__ gate_w)
{
    __shared__ __align__(16) float srow[18 * 512];   // 36 KB
    __shared__ float s_w;
    int ya  = blockIdx.x * 32;
    int bc  = blockIdx.y;
    int s   = blockIdx.z;
    int b   = bc >> 1, c = bc & 1;
    int tid = threadIdx.x;

    // gate: one warp, shuffle reduction over k=0..63
    if (tid < 32) {
        float acc = t_emb[b * 64 + tid]      * gate_w[tid * 4 + s]
                  + t_emb[b * 64 + tid + 32] * gate_w[(tid + 32) * 4 + s];
        #pragma unroll
        for (int o = 16; o; o >>= 1)
            acc += __shfl_xor_sync(0xffffffffu, acc, o);
        if (tid == 0)
            s_w = (s == 0 ? 0.5f : 1.0f) / (1.0f + expf(-acc));
    }

    int n, stride;
    const float* srcA;
    const float* srcB = 0;
    if      (s == 0) { n = M4; stride = S4; srcA = g_cA4 + (size_t)bc * M4 * S4;
                                            srcB = g_m4  + (size_t)bc * M4 * S4; }
    else if (s == 1) { n = M3; stride = S3; srcA = g_m3 + (size_t)bc * M3 * S3; }
    else if (s == 2) { n = M2; stride = S2; srcA = g_m2 + (size_t)bc * M2 * S2; }
    else             { n = M1; stride = S1; srcA = g_m1 + (size_t)bc * M1 * S1; }

    float rr = n * (1.0f / 512.0f);
    int i0a  = (int)floorf((ya + 0.5f)  * rr - 0.5f);
    int i1b  = (int)floorf((ya + 31.5f) * rr - 0.5f) + 1;
    int rloC = max(i0a, 0);
    int rhiC = min(i1b, n - 1);
    int nst  = rhiC - rloC + 1;    // <= 18

    // x coords for the two column halves this thread owns
    int xA0, xA1, xB0, xB1; float fA, fB;
    coord(tid,       n, xA0, xA1, fA);
    coord(tid + 256, n, xB0, xB1, fB);

    for (int r = 0; r < nst; r++) {
        const float* rowA = srcA + (size_t)(rloC + r) * stride;
        float a0 = rowA[xA0];
        float vA = a0 + (rowA[xA1] - a0) * fA;
        float b0 = rowA[xB0];
        float vB = b0 + (rowA[xB1] - b0) * fB;
        if (srcB) {
            const float* rowB = srcB + (size_t)(rloC + r) * stride;
            float c0 = rowB[xA0];
            vA += c0 + (rowB[xA1] - c0) * fA;
            float c1 = rowB[xB0];
            vB += c1 + (rowB[xB1] - c1) * fB;
        }
        srow[r * 512 + tid]       = vA;
        srow[r * 512 + tid + 256] = vB;
    }
    __syncthreads();

    float w = s_w;
    size_t obase = ((size_t)(b * 8 + c * 4 + s)) * HW;
    #pragma unroll 4
    for (int i = tid; i < 32 * 128; i += 256) {
        int ry = i >> 7, c4 = i & 127;
        int y = ya + ry;
        int y0, y1; float fy;
        coord(y, n, y0, y1, fy);
        const float4* r0 = reinterpret_cast<const float4*>(srow + (size_t)(y0 - rloC) * 512);
        const float4* r1 = reinterpret_cast<const float4*>(srow + (size_t)(y1 - rloC) * 512);
        float4 a = r0[c4], d = r1[c4], v;
        v.x = (a.x + (d.x - a.x) * fy) * w;
        v.y = (a.y + (d.y - a.y) * fy) * w;
        v.z = (a.z + (d.z - a.z) * fy) * w;
        v.w = (a.w + (d.w - a.w) * fy) * w;
        reinterpret_cast<float4*>(out + obase + (size_t)y * 512)[c4] = v;
    }
}

// ---------------- launch ----------------
extern "C" void kernel_launch(void* const* d_in, const int* in_sizes, int n_in,
                              void* d_out, int out_size)
{
    const float* image  = (const float*)d_in[0];
    const float* t_emb  = (const float*)d_in[1];
    const float* gate_w = (const float*)d_in[2];
    float* out = (float*)d_out;

    float *cA1, *m1, *cA2, *m2, *m3, *cA4, *m4;
    cudaGetSymbolAddress((void**)&cA1, g_cA1);
    cudaGetSymbolAddress((void**)&m1,  g_m1);
    cudaGetSymbolAddress((void**)&cA2, g_cA2);
    cudaGetSymbolAddress((void**)&m2,  g_m2);
    cudaGetSymbolAddress((void**)&m3,  g_m3);
    cudaGetSymbolAddress((void**)&cA4, g_cA4);
    cudaGetSymbolAddress((void**)&m4,  g_m4);

    dim3 blk(32, 8);
    {   dim3 g((M1 + 31) / 32, (M1 + 31) / 32, BC);
        dwt_kernel<512, 512, M1, S1><<<g, blk>>>(image, cA1, m1); }
    {   dim3 g((M2 + 31) / 32, (M2 + 31) / 32, BC);
        dwt_kernel<M1, S1, M2, S2><<<g, blk>>>(cA1, cA2, m2); }

    tail_kernel<<<BC * 8, 256>>>(cA2, m3, cA4, m4);

    up_kernel<<<dim3(16, BC, 4), 256>>>(out, t_emb, gate_w);
}